// round 5
// baseline (speedup 1.0000x reference)
#include <cuda_runtime.h>
#include <cstdint>

// Chamfer distance: array1, array2 [B=4, N=4096, D=3] fp32.
// out = (100 / 32768) * sum of per-point nearest-neighbor sq-dists (both dirs).
//
// d2 = |a|^2 + |b|^2 - 2 a.b.  Inner points in smem DUPLICATED per point as
// (x,x,y,y,z,z,w,w), w = -0.5*|y|^2, so packed fma.rn.f32x2 (FFMA2) processes
// TWO outer points per instruction.  min d2 = |a|^2 - 2*max(t).
//
// R5: BLK=1024 (32 warps) -> 8 warps/SMSP. R4 (4/SMSP) was latency-bound at
// issue=40.7%, fma=30.7%: LDS(29cyc) + 3-deep FFMA2 chains exposed. Grid 16x8
// = 128 blocks = one wave, 1 CTA/SM. Each warp owns 1/32 of the inner tile;
// each thread owns PT=8 outer points (4 packed pairs). Inner dim streamed in
// 4 passes of 1024 pts (32 B/pt = 32 KB smem). Cross-warp combine (32x256
// floats = 32 KB) OVERLAYS the tile buffer. Last block (atomic counter,
// fixed-order read) does the final sum -> single fused kernel.

#define BLK 1024
#define NWARP 32
#define PT 8
#define OUTER_PER_BLOCK 256
#define NCHUNK 16
#define NPTS 4096
#define PASS_PTS 1024
#define NPASS 4
#define SLICE 32             // PASS_PTS / NWARP
#define NBLOCKS 128

__device__ float g_partial[NBLOCKS];
__device__ int   g_count;    // zero-init; self-resets each run

__device__ __forceinline__ unsigned long long pack2(float lo, float hi) {
    unsigned long long r;
    asm("mov.b64 %0, {%1, %2};" : "=l"(r) : "f"(lo), "f"(hi));
    return r;
}
__device__ __forceinline__ unsigned long long fma2(
    unsigned long long a, unsigned long long b, unsigned long long c) {
    unsigned long long d;
    asm("fma.rn.f32x2 %0, %1, %2, %3;" : "=l"(d) : "l"(a), "l"(b), "l"(c));
    return d;
}
__device__ __forceinline__ void unpack2(unsigned long long v, float& lo, float& hi) {
    asm("mov.b64 {%0, %1}, %2;" : "=f"(lo), "=f"(hi) : "l"(v));
}

__global__ __launch_bounds__(BLK, 1) void chamfer_main(
    const float* __restrict__ a1, const float* __restrict__ a2,
    float* __restrict__ out)
{
    // 32 KB buffer: duplicated inner tile during passes; after the last pass,
    // reused as the 32x256 cross-warp combine array (32 KB).
    __shared__ __align__(16) float sbuf[PASS_PTS * 8];
    __shared__ float s_red[NWARP];
    __shared__ int   s_last;

    const int t   = threadIdx.x;
    const int wi  = t >> 5;            // warp id 0..31 = inner slice
    const int l   = t & 31;
    const int z   = blockIdx.y;        // 0..7 = b*2 + dir
    const int b   = z >> 1;
    const int dir = z & 1;

    const float* xb = (dir ? a2 : a1) + (size_t)b * NPTS * 3;
    const float* yb = (dir ? a1 : a2) + (size_t)b * NPTS * 3;

    // PT=8 outer points per lane (shared across all 32 warps), packed pairwise
    const int n0 = blockIdx.x * OUTER_PER_BLOCK + l;
    unsigned long long ax2[4], ay2[4], az2[4];
    float sq[PT], m[PT];
#pragma unroll
    for (int j = 0; j < 4; j++) {
        const int na = n0 + (2 * j) * 32;
        const int nb = na + 32;
        const float xa = xb[na * 3 + 0], ya = xb[na * 3 + 1], za = xb[na * 3 + 2];
        const float xc = xb[nb * 3 + 0], yc = xb[nb * 3 + 1], zc = xb[nb * 3 + 2];
        ax2[j] = pack2(xa, xc);
        ay2[j] = pack2(ya, yc);
        az2[j] = pack2(za, zc);
        sq[2 * j + 0] = xa * xa + ya * ya + za * za;
        sq[2 * j + 1] = xc * xc + yc * yc + zc * zc;
        m[2 * j + 0] = -3.0e38f;
        m[2 * j + 1] = -3.0e38f;
    }

#pragma unroll 1
    for (int pass = 0; pass < NPASS; pass++) {
        __syncthreads();   // previous tile fully consumed
        if (t < 256) {     // threads 0..255 fill 4 points each (3 float4 loads)
            const float4* ysrc = (const float4*)yb + (size_t)pass * (PASS_PTS * 3 / 4);
            const float4 A = ysrc[t * 3 + 0];
            const float4 B = ysrc[t * 3 + 1];
            const float4 C = ysrc[t * 3 + 2];
            float4* sp = (float4*)sbuf + (size_t)t * 8;
            float px, py, pz, pw;
            px = A.x; py = A.y; pz = A.z; pw = -0.5f * (px*px + py*py + pz*pz);
            sp[0] = make_float4(px, px, py, py);
            sp[1] = make_float4(pz, pz, pw, pw);
            px = A.w; py = B.x; pz = B.y; pw = -0.5f * (px*px + py*py + pz*pz);
            sp[2] = make_float4(px, px, py, py);
            sp[3] = make_float4(pz, pz, pw, pw);
            px = B.z; py = B.w; pz = C.x; pw = -0.5f * (px*px + py*py + pz*pz);
            sp[4] = make_float4(px, px, py, py);
            sp[5] = make_float4(pz, pz, pw, pw);
            px = C.y; py = C.z; pz = C.w; pw = -0.5f * (px*px + py*py + pz*pz);
            sp[6] = make_float4(px, px, py, py);
            sp[7] = make_float4(pz, pz, pw, pw);
        }
        __syncthreads();

        // warp wi scans its 32-point slice; broadcast LDS.128 loads
        const ulonglong2* syp = (const ulonglong2*)sbuf + (size_t)wi * SLICE * 2;
#pragma unroll 4
        for (int i = 0; i < SLICE; i++) {
            const ulonglong2 v0 = syp[2 * i + 0];   // (x,x) (y,y)
            const ulonglong2 v1 = syp[2 * i + 1];   // (z,z) (w,w)
#pragma unroll
            for (int j = 0; j < 4; j++) {
                unsigned long long tt = fma2(az2[j], v1.x, v1.y);
                tt = fma2(ay2[j], v0.y, tt);
                tt = fma2(ax2[j], v0.x, tt);
                float lo, hi;
                unpack2(tt, lo, hi);
                m[2 * j + 0] = fmaxf(m[2 * j + 0], lo);
                m[2 * j + 1] = fmaxf(m[2 * j + 1], hi);
            }
        }
    }
    __syncthreads();   // tile dead; sbuf becomes the combine array

    float (*s_part)[OUTER_PER_BLOCK] = (float (*)[OUTER_PER_BLOCK])sbuf;
#pragma unroll
    for (int k = 0; k < PT; k++)
        s_part[wi][l + k * 32] = sq[k] - 2.0f * m[k];
    __syncthreads();

    // first 256 threads: min across the 32 inner slices, then block-sum
    float v = 0.0f;
    if (t < 256) {
        v = s_part[0][t];
#pragma unroll
        for (int g = 1; g < NWARP; g++) v = fminf(v, s_part[g][t]);
    }
#pragma unroll
    for (int o = 16; o; o >>= 1) v += __shfl_down_sync(0xffffffffu, v, o);
    if (l == 0) s_red[wi] = v;     // warps 8..31 contribute 0
    __syncthreads();

    if (t == 0) {
        float r = 0.0f;
#pragma unroll
        for (int g = 0; g < 8; g++) r += s_red[g];
        g_partial[blockIdx.y * NCHUNK + blockIdx.x] = r;
        __threadfence();
        const int old = atomicAdd(&g_count, 1);
        s_last = (old == NBLOCKS - 1);
    }
    __syncthreads();

    // last block: warp 0 sums the 128 partials in fixed order (deterministic)
    if (s_last && wi == 0) {
        __threadfence();
        float s = 0.0f;
#pragma unroll
        for (int q = 0; q < NBLOCKS / 32; q++) s += g_partial[l + q * 32];
#pragma unroll
        for (int o = 16; o; o >>= 1) s += __shfl_down_sync(0xffffffffu, s, o);
        if (l == 0) {
            out[0] = s * (100.0f / 32768.0f);
            g_count = 0;    // reset for next graph replay
        }
    }
}

extern "C" void kernel_launch(void* const* d_in, const int* in_sizes, int n_in,
                              void* d_out, int out_size)
{
    const float* a1 = (const float*)d_in[0];
    const float* a2 = (const float*)d_in[1];
    float* out = (float*)d_out;

    dim3 grid(NCHUNK, 8);               // 16 x 8 = 128 blocks, one wave
    chamfer_main<<<grid, BLK>>>(a1, a2, out);
}

// round 6
// speedup vs baseline: 1.1872x; 1.1872x over previous
#include <cuda_runtime.h>

// Chamfer distance: array1, array2 [B=4, N=4096, D=3] fp32.
// out = (100 / 32768) * sum of per-point nearest-neighbor sq-dists (both dirs).
//
// d2 = |a|^2 + |b|^2 - 2 a.b.  smem tile holds (y.x, y.y, y.z, -0.5*|y|^2) per
// inner point; per pair: t = fma(ax, px, fma(ay, py, fma(az, pz, pw))), track
// max t; min d2 = |a|^2 - 2*max(t).  SCALAR FFMA (rt=2) — the packed f32x2
// experiments (R3-R5) lost to RF-bank rt=3 + pair-marshalling and never beat
// the scalar R2 loop.  1 broadcast LDS.128 amortized over PT=8 outer points;
// 8 independent max chains give ILP.
//
// BLK=512 (16 warps -> 4 warps/SMSP, no reg cap), grid 16x8 = 128 blocks = one
// wave.  Each warp owns 1/16 of the inner tile; inner dim streamed in 2 passes
// of 2048 pts (16 B/pt = 32 KB smem).  Cross-warp combine (16x256 = 16 KB)
// OVERLAYS the dead tile buffer.  Last block (atomic counter, fixed-order
// read) does the final sum -> single fused kernel, no second launch.

#define BLK 512
#define NWARP 16
#define PT 8
#define OUTER_PER_BLOCK 256
#define NCHUNK 16
#define NPTS 4096
#define PASS_PTS 2048
#define NPASS 2
#define SLICE 128            // PASS_PTS / NWARP
#define NBLOCKS 128

__device__ float g_partial[NBLOCKS];
__device__ int   g_count;    // zero-init; self-resets each run

__global__ __launch_bounds__(BLK) void chamfer_main(
    const float* __restrict__ a1, const float* __restrict__ a2,
    float* __restrict__ out)
{
    // 32 KB buffer: inner tile during passes; reused as the 16x256 combine
    // array after the last pass.
    __shared__ __align__(16) float4 sbuf[PASS_PTS];
    __shared__ float s_red[NWARP];
    __shared__ int   s_last;

    const int t   = threadIdx.x;
    const int wi  = t >> 5;            // warp id 0..15 = inner slice
    const int l   = t & 31;
    const int z   = blockIdx.y;        // 0..7 = b*2 + dir
    const int b   = z >> 1;
    const int dir = z & 1;

    const float* xb = (dir ? a2 : a1) + (size_t)b * NPTS * 3;
    const float* yb = (dir ? a1 : a2) + (size_t)b * NPTS * 3;

    // PT=8 outer points per lane (shared across all 16 warps)
    const int n0 = blockIdx.x * OUTER_PER_BLOCK + l;
    float ax[PT], ay[PT], az[PT], sq[PT], m[PT];
#pragma unroll
    for (int k = 0; k < PT; k++) {
        const int n = n0 + k * 32;
        ax[k] = xb[n * 3 + 0];
        ay[k] = xb[n * 3 + 1];
        az[k] = xb[n * 3 + 2];
        sq[k] = ax[k] * ax[k] + ay[k] * ay[k] + az[k] * az[k];
        m[k]  = -3.0e38f;
    }

#pragma unroll 1
    for (int pass = 0; pass < NPASS; pass++) {
        __syncthreads();   // previous tile fully consumed
        {   // all 512 threads fill 4 points each (3 float4 LDG, 4 STS.128)
            const float4* ysrc = (const float4*)yb + (size_t)pass * (PASS_PTS * 3 / 4);
            const float4 A = ysrc[t * 3 + 0];
            const float4 B = ysrc[t * 3 + 1];
            const float4 C = ysrc[t * 3 + 2];
            sbuf[t * 4 + 0] = make_float4(A.x, A.y, A.z,
                -0.5f * (A.x * A.x + A.y * A.y + A.z * A.z));
            sbuf[t * 4 + 1] = make_float4(A.w, B.x, B.y,
                -0.5f * (A.w * A.w + B.x * B.x + B.y * B.y));
            sbuf[t * 4 + 2] = make_float4(B.z, B.w, C.x,
                -0.5f * (B.z * B.z + B.w * B.w + C.x * C.x));
            sbuf[t * 4 + 3] = make_float4(C.y, C.z, C.w,
                -0.5f * (C.y * C.y + C.z * C.z + C.w * C.w));
        }
        __syncthreads();

        // warp wi scans its 128-point slice; broadcast LDS.128
        const float4* syp = sbuf + (size_t)wi * SLICE;
#pragma unroll 4
        for (int i = 0; i < SLICE; i++) {
            const float4 p = syp[i];
#pragma unroll
            for (int k = 0; k < PT; k++) {
                const float tt = fmaf(ax[k], p.x,
                                 fmaf(ay[k], p.y,
                                 fmaf(az[k], p.z, p.w)));
                m[k] = fmaxf(m[k], tt);
            }
        }
    }
    __syncthreads();   // tile dead; sbuf becomes the combine array

    float (*s_part)[OUTER_PER_BLOCK] = (float (*)[OUTER_PER_BLOCK])sbuf;
#pragma unroll
    for (int k = 0; k < PT; k++)
        s_part[wi][l + k * 32] = sq[k] - 2.0f * m[k];
    __syncthreads();

    // first 256 threads: min across the 16 inner slices, then block-sum
    float v = 0.0f;
    if (t < 256) {
        v = s_part[0][t];
#pragma unroll
        for (int g = 1; g < NWARP; g++) v = fminf(v, s_part[g][t]);
    }
#pragma unroll
    for (int o = 16; o; o >>= 1) v += __shfl_down_sync(0xffffffffu, v, o);
    if (l == 0) s_red[wi] = v;     // warps 8..15 contribute 0
    __syncthreads();

    if (t == 0) {
        float r = 0.0f;
#pragma unroll
        for (int g = 0; g < 8; g++) r += s_red[g];
        g_partial[blockIdx.y * NCHUNK + blockIdx.x] = r;
        __threadfence();
        const int old = atomicAdd(&g_count, 1);
        s_last = (old == NBLOCKS - 1);
    }
    __syncthreads();

    // last block: warp 0 sums the 128 partials in fixed order (deterministic)
    if (s_last && wi == 0) {
        __threadfence();
        float s = 0.0f;
#pragma unroll
        for (int q = 0; q < NBLOCKS / 32; q++) s += g_partial[l + q * 32];
#pragma unroll
        for (int o = 16; o; o >>= 1) s += __shfl_down_sync(0xffffffffu, s, o);
        if (l == 0) {
            out[0] = s * (100.0f / 32768.0f);
            g_count = 0;    // reset for next graph replay
        }
    }
}

extern "C" void kernel_launch(void* const* d_in, const int* in_sizes, int n_in,
                              void* d_out, int out_size)
{
    const float* a1 = (const float*)d_in[0];
    const float* a2 = (const float*)d_in[1];
    float* out = (float*)d_out;

    dim3 grid(NCHUNK, 8);               // 16 x 8 = 128 blocks, one wave
    chamfer_main<<<grid, BLK>>>(a1, a2, out);
}